// round 13
// baseline (speedup 1.0000x reference)
#include <cuda_runtime.h>
#include <cstdint>

#define MAXN 100000
typedef unsigned long long ull;

// ---------------- device scratch (static: no allocations allowed) ----------------
__device__ float  g_bn[8];              // sum[4], sumsq[4]
__device__ float  g_deg[MAXN];
__device__ float4 g_enc_acc[MAXN];      // {mu0,mu1,lv0,lv1} sums
__device__ float4 g_dec_acc[MAXN];      // {o0..o3} sums
__device__ float4 g_ea[MAXN * 8];       // A@xn + b1  (N x 32)
__device__ float4 g_eb[MAXN * 8];       // B@xn       (N x 32)
__device__ float4 g_da[MAXN * 8];       // decoder A@z + b1
__device__ float4 g_db[MAXN * 8];       // decoder B@z

__device__ __forceinline__ void red_add_v4(float* p, float a, float b, float c, float d) {
    asm volatile("red.global.add.v4.f32 [%0], {%1,%2,%3,%4};"
                 :: "l"(p), "f"(a), "f"(b), "f"(c), "f"(d) : "memory");
}
__device__ __forceinline__ void red_add_f32(float* p, float a) {
    asm volatile("red.global.add.f32 [%0], %1;" :: "l"(p), "f"(a) : "memory");
}
__device__ __forceinline__ ull pack2(float lo, float hi) {
    ull d;
    asm("mov.b64 %0, {%1, %2};" : "=l"(d) : "f"(lo), "f"(hi));
    return d;
}
__device__ __forceinline__ void unpack2(ull v, float& lo, float& hi) {
    asm("mov.b64 {%0, %1}, %2;" : "=f"(lo), "=f"(hi) : "l"(v));
}
// pack two f32 to f16x2: hi -> high half, lo -> low half
__device__ __forceinline__ uint32_t cvt_h2(float hi, float lo) {
    uint32_t r;
    asm("cvt.rn.f16x2.f32 %0, %1, %2;" : "=r"(r) : "f"(hi), "f"(lo));
    return r;
}
__device__ __forceinline__ uint32_t smem_u32(const void* p) {
    uint32_t a;
    asm("{ .reg .u64 t; cvta.to.shared.u64 t, %1; cvt.u32.u64 %0, t; }" : "=r"(a) : "l"(p));
    return a;
}
__device__ __forceinline__ void ldsm_x4(uint32_t& r0, uint32_t& r1, uint32_t& r2, uint32_t& r3,
                                        uint32_t addr) {
    asm volatile("ldmatrix.sync.aligned.m8n8.x4.shared.b16 {%0,%1,%2,%3}, [%4];"
                 : "=r"(r0), "=r"(r1), "=r"(r2), "=r"(r3) : "r"(addr));
}

// ---------------- zero accumulators ----------------
__global__ void k_zero(int n) {
    int t = blockIdx.x * blockDim.x + threadIdx.x;
    int stride = gridDim.x * blockDim.x;
    float4 z = make_float4(0.f, 0.f, 0.f, 0.f);
    for (int i = t; i < n; i += stride) {
        g_enc_acc[i] = z;
        g_dec_acc[i] = z;
        g_deg[i] = 0.f;
    }
    if (t < 8) g_bn[t] = 0.f;
}

// ---------------- batchnorm statistics ----------------
__global__ void k_bn_reduce(const float4* __restrict__ x, int n) {
    int t = blockIdx.x * blockDim.x + threadIdx.x;
    int stride = gridDim.x * blockDim.x;
    float s[4] = {0.f, 0.f, 0.f, 0.f};
    float q[4] = {0.f, 0.f, 0.f, 0.f};
    for (int i = t; i < n; i += stride) {
        float4 v = x[i];
        s[0] += v.x; q[0] += v.x * v.x;
        s[1] += v.y; q[1] += v.y * v.y;
        s[2] += v.z; q[2] += v.z * v.z;
        s[3] += v.w; q[3] += v.w * v.w;
    }
#pragma unroll
    for (int o = 16; o > 0; o >>= 1) {
#pragma unroll
        for (int c = 0; c < 4; c++) {
            s[c] += __shfl_down_sync(0xffffffffu, s[c], o);
            q[c] += __shfl_down_sync(0xffffffffu, q[c], o);
        }
    }
    if ((threadIdx.x & 31) == 0) {
#pragma unroll
        for (int c = 0; c < 4; c++) {
            atomicAdd(&g_bn[c], s[c]);
            atomicAdd(&g_bn[4 + c], q[c]);
        }
    }
}

// ---------------- encoder node precompute: BN + linearized layer 1 ----------------
__global__ void k_prep_enc(const float4* __restrict__ x,
                           const float* __restrict__ w1, const float* __restrict__ b1,
                           const float* __restrict__ gamma, const float* __restrict__ beta,
                           int n) {
    __shared__ float sw[256];   // enc_w1 (32 x 8) row-major
    __shared__ float sb1[32];
    __shared__ float sm[4], ss[4], sbt[4];
    int tid = threadIdx.x;
    if (tid < 256) sw[tid] = w1[tid];
    if (tid < 32)  sb1[tid] = b1[tid];
    if (tid < 4) {
        float m = g_bn[tid] / (float)n;
        float var = g_bn[4 + tid] / (float)n - m * m;
        sm[tid]  = m;
        ss[tid]  = rsqrtf(var + 1e-5f) * gamma[tid];
        sbt[tid] = beta[tid];
    }
    __syncthreads();
    int t = blockIdx.x * blockDim.x + tid;
    int stride = gridDim.x * blockDim.x;
    for (int i = t; i < n; i += stride) {
        float4 xv = x[i];
        float x0 = (xv.x - sm[0]) * ss[0] + sbt[0];
        float x1 = (xv.y - sm[1]) * ss[1] + sbt[1];
        float x2 = (xv.z - sm[2]) * ss[2] + sbt[2];
        float x3 = (xv.w - sm[3]) * ss[3] + sbt[3];
        float4 ra[8], rb[8];
        float* pa = (float*)ra;
        float* pb = (float*)rb;
#pragma unroll
        for (int k = 0; k < 32; k++) {
            const float* w = sw + k * 8;
            float b = w[4] * x0 + w[5] * x1 + w[6] * x2 + w[7] * x3;
            float a = sb1[k] + w[0] * x0 + w[1] * x1 + w[2] * x2 + w[3] * x3 - b;
            pa[k] = a;
            pb[k] = b;
        }
#pragma unroll
        for (int q8 = 0; q8 < 8; q8++) {
            g_ea[i * 8 + q8] = ra[q8];
            g_eb[i * 8 + q8] = rb[q8];
        }
    }
}

// ---------------- per-edge kernel: fp16 staged gather -> ldmatrix f16 MMA -> chained f16 MMA -> RED ----
// Warp-tile = 64 edges. A = fp16 u rows [64x32] in warp-private smem, row stride 80B
// (stride-20-word rows: both STS.128 phases and ldmatrix phases hit all 32 banks).
// GEMM1: m16n8k16 f16 (A via ldmatrix.x4, W2 persistent f16 B-frags, bias-seeded f32 acc).
// GEMM2 (projection): relu(C1) in-lane cvt to f16 A-frags, P[32x8] persistent B-frags.
// Outputs in lanes tg=0/1; one 64-bit shfl pairs them; RED v4 + deg.
#define RSH 40   // halves per stage row (80B)
template <int PHASE>
__global__ void __launch_bounds__(128, 4)
k_edge(const int* __restrict__ ei, int E, int n,
       const float* __restrict__ w2, const float* __restrict__ b2,
       const float* __restrict__ pA, const float* __restrict__ pB) {
    __shared__ __align__(16) uint16_t su[4 * 64 * RSH];   // 20.5KB
    __shared__ float s_b2[32];
    int tid = threadIdx.x;
    int warp = tid >> 5, lane = tid & 31;
    int g = lane >> 2, tg = lane & 3;

    if (tid < 32) s_b2[tid] = b2[tid];

    // GEMM1 persistent B fragments (f16): bf0/bf1[nt][ks], n = 8nt+g, k = ks*16 + ...
    uint32_t bf0[4][2], bf1[4][2];
#pragma unroll
    for (int nt = 0; nt < 4; nt++)
#pragma unroll
        for (int ks = 0; ks < 2; ks++) {
            const float* wr = w2 + (8 * nt + g) * 32 + 16 * ks;
            bf0[nt][ks] = cvt_h2(wr[2 * tg + 1], wr[2 * tg]);
            bf1[nt][ks] = cvt_h2(wr[2 * tg + 9], wr[2 * tg + 8]);
        }

    // GEMM2 persistent B fragments: P[k][n], n = g (cols 0-3 real, 4-7 zero)
    auto Pv = [&](int k) -> float {
        return (g == 0) ? pA[k] : (g == 1) ? pA[32 + k]
             : (g == 2) ? pB[k] : (g == 3) ? pB[32 + k] : 0.f;
    };
    uint32_t pb0[2], pb1[2];
#pragma unroll
    for (int m = 0; m < 2; m++) {
        int k0 = 16 * m + 2 * tg;
        pb0[m] = cvt_h2(Pv(k0 + 1), Pv(k0));
        pb1[m] = cvt_h2(Pv(k0 + 9), Pv(k0 + 8));
    }
    __syncthreads();

    const float4* fa = (PHASE == 0) ? g_ea : g_da;
    const float4* fb = (PHASE == 0) ? g_eb : g_db;
    float* acc = (PHASE == 0) ? (float*)g_enc_acc : (float*)g_dec_acc;

    uint16_t* stage = su + warp * 64 * RSH;
    uint32_t stage_s = smem_u32(stage);
    int sub = lane >> 3, rsub = lane & 7;   // gather: 8 rows per pass, 4 chunk-lanes per row
    // ldmatrix lane address: matrix = lane>>3 (0..3), row-in-8 = lane&7
    int lm_mat = lane >> 3, lm_r8 = lane & 7;
    uint32_t lm_base = stage_s + (uint32_t)((lm_mat & 1) * 8 + lm_r8) * (RSH * 2)
                     + (uint32_t)(lm_mat >> 1) * 16;
    int ntiles = (E + 255) >> 8;   // 256 edges per block-tile (64 per warp)

    for (int t = blockIdx.x; t < ntiles; t += gridDim.x) {
        int base = (t << 8) + (warp << 6);
        int eA = base + lane;
        int eB = base + 32 + lane;
        bool okA = (eA < E), okB = (eB < E);
        int eAc = okA ? eA : (E - 1);
        int eBc = okB ? eB : (E - 1);
        unsigned jA = (unsigned)ei[eAc];
        unsigned iA = (unsigned)ei[E + eAc];
        unsigned jB = (unsigned)ei[eBc];
        unsigned iB = (unsigned)ei[E + eBc];
        okA = okA && (jA < (unsigned)n) && (iA < (unsigned)n);
        okB = okB && (jB < (unsigned)n) && (iB < (unsigned)n);
        unsigned jsA = okA ? jA : 0u, isA = okA ? iA : 0u;
        unsigned jsB = okB ? jB : 0u, isB = okB ? iB : 0u;
        unsigned okiA = okA ? 1u : 0u, okiB = okB ? 1u : 0u;

        __syncwarp();   // stage is warp-private; prior iter reads done
#pragma unroll
        for (int h = 0; h < 2; h++) {
#pragma unroll
            for (int p = 0; p < 4; p++) {
                int er = p * 8 + rsub;
                unsigned nd = __shfl_sync(0xffffffffu, h ? isB : isA, er);
                unsigned ns = __shfl_sync(0xffffffffu, h ? jsB : jsA, er);
                const float4* pa = fa + nd * 8 + sub * 2;
                const float4* pb = fb + ns * 8 + sub * 2;
                float4 a0 = pa[0], a1 = pa[1];
                float4 b0 = pb[0], b1 = pb[1];
                uint4 w;
                w.x = cvt_h2(fmaxf(a0.y + b0.y, 0.f), fmaxf(a0.x + b0.x, 0.f));
                w.y = cvt_h2(fmaxf(a0.w + b0.w, 0.f), fmaxf(a0.z + b0.z, 0.f));
                w.z = cvt_h2(fmaxf(a1.y + b1.y, 0.f), fmaxf(a1.x + b1.x, 0.f));
                w.w = cvt_h2(fmaxf(a1.w + b1.w, 0.f), fmaxf(a1.z + b1.z, 0.f));
                *(uint4*)(stage + (h * 32 + er) * RSH + sub * 8) = w;
            }
        }
        __syncwarp();

#pragma unroll
        for (int mt = 0; mt < 4; mt++) {
            // ---- GEMM1: v = W2 @ u + b2 (bias-seeded), A via ldmatrix ----
            float c[4][4];
#pragma unroll
            for (int nt = 0; nt < 4; nt++) {
                float bb0 = s_b2[8 * nt + 2 * tg];
                float bb1 = s_b2[8 * nt + 2 * tg + 1];
                c[nt][0] = bb0; c[nt][1] = bb1;
                c[nt][2] = bb0; c[nt][3] = bb1;
            }
            uint32_t lm_addr = lm_base + (uint32_t)(mt * 16) * (RSH * 2);
#pragma unroll
            for (int ks = 0; ks < 2; ks++) {
                uint32_t a0, a1, a2, a3;
                ldsm_x4(a0, a1, a2, a3, lm_addr + ks * 32);
#pragma unroll
                for (int nt = 0; nt < 4; nt++) {
                    asm volatile(
                        "mma.sync.aligned.m16n8k16.row.col.f32.f16.f16.f32 "
                        "{%0,%1,%2,%3}, {%4,%5,%6,%7}, {%8,%9}, {%0,%1,%2,%3};"
                        : "+f"(c[nt][0]), "+f"(c[nt][1]), "+f"(c[nt][2]), "+f"(c[nt][3])
                        : "r"(a0), "r"(a1), "r"(a2), "r"(a3),
                          "r"(bf0[nt][ks]), "r"(bf1[nt][ks]));
                }
            }

            // ---- GEMM2: p = relu(v) @ P  (chained fp16, in-lane A-frags) ----
            float d[4] = {0.f, 0.f, 0.f, 0.f};
#pragma unroll
            for (int m = 0; m < 2; m++) {
                int n0 = 2 * m, n1 = 2 * m + 1;
                uint32_t a0 = cvt_h2(fmaxf(c[n0][1], 0.f), fmaxf(c[n0][0], 0.f));
                uint32_t a1 = cvt_h2(fmaxf(c[n0][3], 0.f), fmaxf(c[n0][2], 0.f));
                uint32_t a2 = cvt_h2(fmaxf(c[n1][1], 0.f), fmaxf(c[n1][0], 0.f));
                uint32_t a3 = cvt_h2(fmaxf(c[n1][3], 0.f), fmaxf(c[n1][2], 0.f));
                asm volatile(
                    "mma.sync.aligned.m16n8k16.row.col.f32.f16.f16.f32 "
                    "{%0,%1,%2,%3}, {%4,%5,%6,%7}, {%8,%9}, {%0,%1,%2,%3};"
                    : "+f"(d[0]), "+f"(d[1]), "+f"(d[2]), "+f"(d[3])
                    : "r"(a0), "r"(a1), "r"(a2), "r"(a3),
                      "r"(pb0[m]), "r"(pb1[m]));
            }

            // ---- epilogue: D rows g (d0,d1), g+8 (d2,d3); tg0 = mu01, tg1 = lv01 ----
            ull pk0 = pack2(d[0], d[1]);
            ull pk1 = pack2(d[2], d[3]);
            ull o0 = __shfl_xor_sync(0xffffffffu, pk0, 1);
            ull o1 = __shfl_xor_sync(0xffffffffu, pk1, 1);

            unsigned isH  = (mt < 2) ? isA : isB;
            unsigned okiH = (mt < 2) ? okiA : okiB;
            int rh = (mt & 1) * 16 + g;
            unsigned iR0  = __shfl_sync(0xffffffffu, isH,  rh);
            unsigned okR0 = __shfl_sync(0xffffffffu, okiH, rh);
            unsigned iR1  = __shfl_sync(0xffffffffu, isH,  rh + 8);
            unsigned okR1 = __shfl_sync(0xffffffffu, okiH, rh + 8);
            if (tg == 0) {
                float m0, m1, l0, l1;
                if (okR0) {
                    unpack2(pk0, m0, m1);
                    unpack2(o0, l0, l1);
                    red_add_v4(acc + 4 * iR0, m0, m1, l0, l1);
                }
                if (okR1) {
                    unpack2(pk1, m0, m1);
                    unpack2(o1, l0, l1);
                    red_add_v4(acc + 4 * iR1, m0, m1, l0, l1);
                }
            } else if (PHASE == 0 && tg == 1) {
                if (okR0) red_add_f32(&g_deg[iR0], 1.0f);
                if (okR1) red_add_f32(&g_deg[iR1], 1.0f);
            }
        }
    }
}

// ---------------- finalize encoder: mu/logvar, reparam z, decoder layer-1 precompute ----------------
__global__ void k_fin1(const float2* __restrict__ eps,
                       const float* __restrict__ mu_b, const float* __restrict__ var_b,
                       const float* __restrict__ dw1, const float* __restrict__ db1,
                       float* __restrict__ out, int n, int out_size) {
    __shared__ float sw[128];   // dec_w1 (32 x 4)
    __shared__ float sb[32];
    __shared__ float sc[4];
    int tid = threadIdx.x;
    if (tid < 128) sw[tid] = dw1[tid];
    if (tid < 32)  sb[tid] = db1[tid];
    if (tid < 2) { sc[tid] = mu_b[tid]; sc[2 + tid] = var_b[tid]; }
    __syncthreads();
    bool write_heads = (out_size >= 8 * n);
    float2* out_mu = (float2*)(out + 4 * n);
    float2* out_lv = (float2*)(out + 6 * n);
    int t = blockIdx.x * blockDim.x + tid;
    int stride = gridDim.x * blockDim.x;
    for (int i = t; i < n; i += stride) {
        float4 a = g_enc_acc[i];
        float inv = 1.0f / fmaxf(g_deg[i], 1.0f);
        float mu0 = a.x * inv + sc[0];
        float mu1 = a.y * inv + sc[1];
        float lv0 = a.z * inv + sc[2];
        float lv1 = a.w * inv + sc[3];
        float2 ep = eps[i];
        float z0 = mu0 + ep.x * expf(0.5f * lv0);
        float z1 = mu1 + ep.y * expf(0.5f * lv1);
        if (write_heads) {
            out_mu[i] = make_float2(mu0, mu1);
            out_lv[i] = make_float2(lv0, lv1);
        }
        float4 ra[8], rb[8];
        float* pa = (float*)ra;
        float* pb = (float*)rb;
#pragma unroll
        for (int k = 0; k < 32; k++) {
            const float* w = sw + k * 4;
            float b = w[2] * z0 + w[3] * z1;
            float aa = sb[k] + w[0] * z0 + w[1] * z1 - b;
            pa[k] = aa;
            pb[k] = b;
        }
#pragma unroll
        for (int q8 = 0; q8 < 8; q8++) {
            g_da[i * 8 + q8] = ra[q8];
            g_db[i * 8 + q8] = rb[q8];
        }
    }
}

// ---------------- finalize decoder output ----------------
__global__ void k_fin2(const float* __restrict__ b3, float4* __restrict__ out, int n) {
    int t = blockIdx.x * blockDim.x + threadIdx.x;
    int stride = gridDim.x * blockDim.x;
    float c0 = b3[0], c1 = b3[1], c2 = b3[2], c3 = b3[3];
    for (int i = t; i < n; i += stride) {
        float4 a = g_dec_acc[i];
        float d = g_deg[i];
        float4 o;
        if (d > 0.5f) {
            float inv = 1.0f / d;
            o = make_float4(a.x * inv + c0, a.y * inv + c1, a.z * inv + c2, a.w * inv + c3);
        } else {
            o = make_float4(0.f, 0.f, 0.f, 0.f);
        }
        out[i] = o;
    }
}

// ---------------- launch ----------------
extern "C" void kernel_launch(void* const* d_in, const int* in_sizes, int n_in,
                              void* d_out, int out_size) {
    const float* x     = (const float*)d_in[0];
    const float* eps   = (const float*)d_in[1];
    const float* gamma = (const float*)d_in[2];
    const float* beta  = (const float*)d_in[3];
    const float* ew1   = (const float*)d_in[4];
    const float* eb1   = (const float*)d_in[5];
    const float* ew2   = (const float*)d_in[6];
    const float* eb2   = (const float*)d_in[7];
    const float* muw   = (const float*)d_in[8];
    const float* mub   = (const float*)d_in[9];
    const float* vw    = (const float*)d_in[10];
    const float* vb    = (const float*)d_in[11];
    const float* dw1   = (const float*)d_in[12];
    const float* db1   = (const float*)d_in[13];
    const float* dw2   = (const float*)d_in[14];
    const float* db2   = (const float*)d_in[15];
    const float* dw3   = (const float*)d_in[16];
    const float* db3   = (const float*)d_in[17];
    const int*   ei    = (const int*)d_in[18];   // int32

    int n = in_sizes[0] / 4;
    int E = in_sizes[18] / 2;
    float* out = (float*)d_out;

    k_zero<<<256, 256>>>(n);
    k_bn_reduce<<<160, 256>>>((const float4*)x, n);
    k_prep_enc<<<256, 256>>>((const float4*)x, ew1, eb1, gamma, beta, n);

    int eblocks = 1184;   // grid-stride over 12500 tiles of 256 edges
    k_edge<0><<<eblocks, 128>>>(ei, E, n, ew2, eb2, muw, vw);
    k_fin1<<<256, 256>>>((const float2*)eps, mub, vb, dw1, db1, out, n, out_size);
    k_edge<1><<<eblocks, 128>>>(ei, E, n, dw2, db2, dw3, dw3 + 64);
    k_fin2<<<128, 256>>>(db3, (float4*)out, n);
}

// round 14
// speedup vs baseline: 1.9398x; 1.9398x over previous
#include <cuda_runtime.h>
#include <cstdint>

#define MAXN 100000
typedef unsigned long long ull;

// ---------------- device scratch (static: no allocations allowed) ----------------
__device__ float  g_bn[8];              // sum[4], sumsq[4]
__device__ float  g_deg[MAXN];
__device__ float4 g_enc_acc[MAXN];      // {mu0,mu1,lv0,lv1} sums
__device__ float4 g_dec_acc[MAXN];      // {o0..o3} sums
__device__ float4 g_ea[MAXN * 8];       // A@xn + b1  (N x 32)
__device__ float4 g_eb[MAXN * 8];       // B@xn       (N x 32)
__device__ float4 g_da[MAXN * 8];       // decoder A@z + b1
__device__ float4 g_db[MAXN * 8];       // decoder B@z

__device__ __forceinline__ void red_add_v4(float* p, float a, float b, float c, float d) {
    asm volatile("red.global.add.v4.f32 [%0], {%1,%2,%3,%4};"
                 :: "l"(p), "f"(a), "f"(b), "f"(c), "f"(d) : "memory");
}
__device__ __forceinline__ void red_add_f32(float* p, float a) {
    asm volatile("red.global.add.f32 [%0], %1;" :: "l"(p), "f"(a) : "memory");
}
__device__ __forceinline__ ull pack2(float lo, float hi) {
    ull d;
    asm("mov.b64 %0, {%1, %2};" : "=l"(d) : "f"(lo), "f"(hi));
    return d;
}
__device__ __forceinline__ void unpack2(ull v, float& lo, float& hi) {
    asm("mov.b64 {%0, %1}, %2;" : "=f"(lo), "=f"(hi) : "l"(v));
}
// pack two f32 to f16x2: hi -> high half, lo -> low half
__device__ __forceinline__ uint32_t cvt_h2(float hi, float lo) {
    uint32_t r;
    asm("cvt.rn.f16x2.f32 %0, %1, %2;" : "=r"(r) : "f"(hi), "f"(lo));
    return r;
}
__device__ __forceinline__ uint32_t smem_u32(const void* p) {
    uint32_t a;
    asm("{ .reg .u64 t; cvta.to.shared.u64 t, %1; cvt.u32.u64 %0, t; }" : "=r"(a) : "l"(p));
    return a;
}
__device__ __forceinline__ void ldsm_x4(uint32_t& r0, uint32_t& r1, uint32_t& r2, uint32_t& r3,
                                        uint32_t addr) {
    asm volatile("ldmatrix.sync.aligned.m8n8.x4.shared.b16 {%0,%1,%2,%3}, [%4];"
                 : "=r"(r0), "=r"(r1), "=r"(r2), "=r"(r3) : "r"(addr));
}

// ---------------- zero accumulators ----------------
__global__ void k_zero(int n) {
    int t = blockIdx.x * blockDim.x + threadIdx.x;
    int stride = gridDim.x * blockDim.x;
    float4 z = make_float4(0.f, 0.f, 0.f, 0.f);
    for (int i = t; i < n; i += stride) {
        g_enc_acc[i] = z;
        g_dec_acc[i] = z;
        g_deg[i] = 0.f;
    }
    if (t < 8) g_bn[t] = 0.f;
}

// ---------------- batchnorm statistics ----------------
__global__ void k_bn_reduce(const float4* __restrict__ x, int n) {
    int t = blockIdx.x * blockDim.x + threadIdx.x;
    int stride = gridDim.x * blockDim.x;
    float s[4] = {0.f, 0.f, 0.f, 0.f};
    float q[4] = {0.f, 0.f, 0.f, 0.f};
    for (int i = t; i < n; i += stride) {
        float4 v = x[i];
        s[0] += v.x; q[0] += v.x * v.x;
        s[1] += v.y; q[1] += v.y * v.y;
        s[2] += v.z; q[2] += v.z * v.z;
        s[3] += v.w; q[3] += v.w * v.w;
    }
#pragma unroll
    for (int o = 16; o > 0; o >>= 1) {
#pragma unroll
        for (int c = 0; c < 4; c++) {
            s[c] += __shfl_down_sync(0xffffffffu, s[c], o);
            q[c] += __shfl_down_sync(0xffffffffu, q[c], o);
        }
    }
    if ((threadIdx.x & 31) == 0) {
#pragma unroll
        for (int c = 0; c < 4; c++) {
            atomicAdd(&g_bn[c], s[c]);
            atomicAdd(&g_bn[4 + c], q[c]);
        }
    }
}

// ---------------- encoder node precompute: BN + linearized layer 1 ----------------
__global__ void k_prep_enc(const float4* __restrict__ x,
                           const float* __restrict__ w1, const float* __restrict__ b1,
                           const float* __restrict__ gamma, const float* __restrict__ beta,
                           int n) {
    __shared__ float sw[256];   // enc_w1 (32 x 8) row-major
    __shared__ float sb1[32];
    __shared__ float sm[4], ss[4], sbt[4];
    int tid = threadIdx.x;
    if (tid < 256) sw[tid] = w1[tid];
    if (tid < 32)  sb1[tid] = b1[tid];
    if (tid < 4) {
        float m = g_bn[tid] / (float)n;
        float var = g_bn[4 + tid] / (float)n - m * m;
        sm[tid]  = m;
        ss[tid]  = rsqrtf(var + 1e-5f) * gamma[tid];
        sbt[tid] = beta[tid];
    }
    __syncthreads();
    int t = blockIdx.x * blockDim.x + tid;
    int stride = gridDim.x * blockDim.x;
    for (int i = t; i < n; i += stride) {
        float4 xv = x[i];
        float x0 = (xv.x - sm[0]) * ss[0] + sbt[0];
        float x1 = (xv.y - sm[1]) * ss[1] + sbt[1];
        float x2 = (xv.z - sm[2]) * ss[2] + sbt[2];
        float x3 = (xv.w - sm[3]) * ss[3] + sbt[3];
        float4 ra[8], rb[8];
        float* pa = (float*)ra;
        float* pb = (float*)rb;
#pragma unroll
        for (int k = 0; k < 32; k++) {
            const float* w = sw + k * 8;
            float b = w[4] * x0 + w[5] * x1 + w[6] * x2 + w[7] * x3;
            float a = sb1[k] + w[0] * x0 + w[1] * x1 + w[2] * x2 + w[3] * x3 - b;
            pa[k] = a;
            pb[k] = b;
        }
#pragma unroll
        for (int q8 = 0; q8 < 8; q8++) {
            g_ea[i * 8 + q8] = ra[q8];
            g_eb[i * 8 + q8] = rb[q8];
        }
    }
}

// ---------------- per-edge kernel: fp16 staged gather -> ldmatrix f16 MMA -> chained f16 MMA -> RED ----
// Warp-tile = 64 edges. A = fp16 u rows [64x32] in warp-private smem, row stride 80B.
// Gather: 4 consecutive lanes cover one contiguous 128B node row (full LDG coalescing);
// minor 2-way STS conflict accepted (~0.25 wf/edge).
// GEMM1: m16n8k16 f16 (A via ldmatrix.x4 — conflict-free at stride 20 words).
// GEMM2 (projection): relu(C1) in-lane cvt to f16 A-frags, P[32x8] persistent B-frags.
// Outputs in lanes tg=0/1; one 64-bit shfl pairs them; RED v4 + deg.
#define RSH 40   // halves per stage row (80B)
template <int PHASE>
__global__ void __launch_bounds__(128, 4)
k_edge(const int* __restrict__ ei, int E, int n,
       const float* __restrict__ w2, const float* __restrict__ b2,
       const float* __restrict__ pA, const float* __restrict__ pB) {
    __shared__ __align__(16) uint16_t su[4 * 64 * RSH];   // 20.5KB
    __shared__ float s_b2[32];
    int tid = threadIdx.x;
    int warp = tid >> 5, lane = tid & 31;
    int g = lane >> 2, tg = lane & 3;

    if (tid < 32) s_b2[tid] = b2[tid];

    // GEMM1 persistent B fragments (f16): bf0/bf1[nt][ks], n = 8nt+g, k = ks*16 + ...
    uint32_t bf0[4][2], bf1[4][2];
#pragma unroll
    for (int nt = 0; nt < 4; nt++)
#pragma unroll
        for (int ks = 0; ks < 2; ks++) {
            const float* wr = w2 + (8 * nt + g) * 32 + 16 * ks;
            bf0[nt][ks] = cvt_h2(wr[2 * tg + 1], wr[2 * tg]);
            bf1[nt][ks] = cvt_h2(wr[2 * tg + 9], wr[2 * tg + 8]);
        }

    // GEMM2 persistent B fragments: P[k][n], n = g (cols 0-3 real, 4-7 zero)
    auto Pv = [&](int k) -> float {
        return (g == 0) ? pA[k] : (g == 1) ? pA[32 + k]
             : (g == 2) ? pB[k] : (g == 3) ? pB[32 + k] : 0.f;
    };
    uint32_t pb0[2], pb1[2];
#pragma unroll
    for (int m = 0; m < 2; m++) {
        int k0 = 16 * m + 2 * tg;
        pb0[m] = cvt_h2(Pv(k0 + 1), Pv(k0));
        pb1[m] = cvt_h2(Pv(k0 + 9), Pv(k0 + 8));
    }
    __syncthreads();

    const float4* fa = (PHASE == 0) ? g_ea : g_da;
    const float4* fb = (PHASE == 0) ? g_eb : g_db;
    float* acc = (PHASE == 0) ? (float*)g_enc_acc : (float*)g_dec_acc;

    uint16_t* stage = su + warp * 64 * RSH;
    uint32_t stage_s = smem_u32(stage);
    int sub = lane & 3, rsub = lane >> 2;   // gather: 4 lanes per row (coalesced), 8 rows per pass
    // ldmatrix lane address: matrix = lane>>3 (0..3), row-in-8 = lane&7
    int lm_mat = lane >> 3, lm_r8 = lane & 7;
    uint32_t lm_base = stage_s + (uint32_t)((lm_mat & 1) * 8 + lm_r8) * (RSH * 2)
                     + (uint32_t)(lm_mat >> 1) * 16;
    int ntiles = (E + 255) >> 8;   // 256 edges per block-tile (64 per warp)

    for (int t = blockIdx.x; t < ntiles; t += gridDim.x) {
        int base = (t << 8) + (warp << 6);
        int eA = base + lane;
        int eB = base + 32 + lane;
        bool okA = (eA < E), okB = (eB < E);
        int eAc = okA ? eA : (E - 1);
        int eBc = okB ? eB : (E - 1);
        unsigned jA = (unsigned)ei[eAc];
        unsigned iA = (unsigned)ei[E + eAc];
        unsigned jB = (unsigned)ei[eBc];
        unsigned iB = (unsigned)ei[E + eBc];
        okA = okA && (jA < (unsigned)n) && (iA < (unsigned)n);
        okB = okB && (jB < (unsigned)n) && (iB < (unsigned)n);
        unsigned jsA = okA ? jA : 0u, isA = okA ? iA : 0u;
        unsigned jsB = okB ? jB : 0u, isB = okB ? iB : 0u;
        unsigned okiA = okA ? 1u : 0u, okiB = okB ? 1u : 0u;

        __syncwarp();   // stage is warp-private; prior iter reads done
#pragma unroll
        for (int h = 0; h < 2; h++) {
#pragma unroll
            for (int p = 0; p < 4; p++) {
                int er = p * 8 + rsub;
                unsigned nd = __shfl_sync(0xffffffffu, h ? isB : isA, er);
                unsigned ns = __shfl_sync(0xffffffffu, h ? jsB : jsA, er);
                const float4* pa = fa + nd * 8 + sub * 2;
                const float4* pb = fb + ns * 8 + sub * 2;
                float4 a0 = pa[0], a1 = pa[1];
                float4 b0 = pb[0], b1 = pb[1];
                uint4 w;
                w.x = cvt_h2(fmaxf(a0.y + b0.y, 0.f), fmaxf(a0.x + b0.x, 0.f));
                w.y = cvt_h2(fmaxf(a0.w + b0.w, 0.f), fmaxf(a0.z + b0.z, 0.f));
                w.z = cvt_h2(fmaxf(a1.y + b1.y, 0.f), fmaxf(a1.x + b1.x, 0.f));
                w.w = cvt_h2(fmaxf(a1.w + b1.w, 0.f), fmaxf(a1.z + b1.z, 0.f));
                *(uint4*)(stage + (h * 32 + er) * RSH + sub * 8) = w;
            }
        }
        __syncwarp();

#pragma unroll
        for (int mt = 0; mt < 4; mt++) {
            // ---- GEMM1: v = W2 @ u + b2 (bias-seeded), A via ldmatrix ----
            float c[4][4];
#pragma unroll
            for (int nt = 0; nt < 4; nt++) {
                float bb0 = s_b2[8 * nt + 2 * tg];
                float bb1 = s_b2[8 * nt + 2 * tg + 1];
                c[nt][0] = bb0; c[nt][1] = bb1;
                c[nt][2] = bb0; c[nt][3] = bb1;
            }
            uint32_t lm_addr = lm_base + (uint32_t)(mt * 16) * (RSH * 2);
#pragma unroll
            for (int ks = 0; ks < 2; ks++) {
                uint32_t a0, a1, a2, a3;
                ldsm_x4(a0, a1, a2, a3, lm_addr + ks * 32);
#pragma unroll
                for (int nt = 0; nt < 4; nt++) {
                    asm volatile(
                        "mma.sync.aligned.m16n8k16.row.col.f32.f16.f16.f32 "
                        "{%0,%1,%2,%3}, {%4,%5,%6,%7}, {%8,%9}, {%0,%1,%2,%3};"
                        : "+f"(c[nt][0]), "+f"(c[nt][1]), "+f"(c[nt][2]), "+f"(c[nt][3])
                        : "r"(a0), "r"(a1), "r"(a2), "r"(a3),
                          "r"(bf0[nt][ks]), "r"(bf1[nt][ks]));
                }
            }

            // ---- GEMM2: p = relu(v) @ P  (chained fp16, in-lane A-frags) ----
            float d[4] = {0.f, 0.f, 0.f, 0.f};
#pragma unroll
            for (int m = 0; m < 2; m++) {
                int n0 = 2 * m, n1 = 2 * m + 1;
                uint32_t a0 = cvt_h2(fmaxf(c[n0][1], 0.f), fmaxf(c[n0][0], 0.f));
                uint32_t a1 = cvt_h2(fmaxf(c[n0][3], 0.f), fmaxf(c[n0][2], 0.f));
                uint32_t a2 = cvt_h2(fmaxf(c[n1][1], 0.f), fmaxf(c[n1][0], 0.f));
                uint32_t a3 = cvt_h2(fmaxf(c[n1][3], 0.f), fmaxf(c[n1][2], 0.f));
                asm volatile(
                    "mma.sync.aligned.m16n8k16.row.col.f32.f16.f16.f32 "
                    "{%0,%1,%2,%3}, {%4,%5,%6,%7}, {%8,%9}, {%0,%1,%2,%3};"
                    : "+f"(d[0]), "+f"(d[1]), "+f"(d[2]), "+f"(d[3])
                    : "r"(a0), "r"(a1), "r"(a2), "r"(a3),
                      "r"(pb0[m]), "r"(pb1[m]));
            }

            // ---- epilogue: D rows g (d0,d1), g+8 (d2,d3); tg0 = mu01, tg1 = lv01 ----
            ull pk0 = pack2(d[0], d[1]);
            ull pk1 = pack2(d[2], d[3]);
            ull o0 = __shfl_xor_sync(0xffffffffu, pk0, 1);
            ull o1 = __shfl_xor_sync(0xffffffffu, pk1, 1);

            unsigned isH  = (mt < 2) ? isA : isB;
            unsigned okiH = (mt < 2) ? okiA : okiB;
            int rh = (mt & 1) * 16 + g;
            unsigned iR0  = __shfl_sync(0xffffffffu, isH,  rh);
            unsigned okR0 = __shfl_sync(0xffffffffu, okiH, rh);
            unsigned iR1  = __shfl_sync(0xffffffffu, isH,  rh + 8);
            unsigned okR1 = __shfl_sync(0xffffffffu, okiH, rh + 8);
            if (tg == 0) {
                float m0, m1, l0, l1;
                if (okR0) {
                    unpack2(pk0, m0, m1);
                    unpack2(o0, l0, l1);
                    red_add_v4(acc + 4 * iR0, m0, m1, l0, l1);
                }
                if (okR1) {
                    unpack2(pk1, m0, m1);
                    unpack2(o1, l0, l1);
                    red_add_v4(acc + 4 * iR1, m0, m1, l0, l1);
                }
            } else if (PHASE == 0 && tg == 1) {
                if (okR0) red_add_f32(&g_deg[iR0], 1.0f);
                if (okR1) red_add_f32(&g_deg[iR1], 1.0f);
            }
        }
    }
}

// ---------------- finalize encoder: mu/logvar, reparam z, decoder layer-1 precompute ----------------
__global__ void k_fin1(const float2* __restrict__ eps,
                       const float* __restrict__ mu_b, const float* __restrict__ var_b,
                       const float* __restrict__ dw1, const float* __restrict__ db1,
                       float* __restrict__ out, int n, int out_size) {
    __shared__ float sw[128];   // dec_w1 (32 x 4)
    __shared__ float sb[32];
    __shared__ float sc[4];
    int tid = threadIdx.x;
    if (tid < 128) sw[tid] = dw1[tid];
    if (tid < 32)  sb[tid] = db1[tid];
    if (tid < 2) { sc[tid] = mu_b[tid]; sc[2 + tid] = var_b[tid]; }
    __syncthreads();
    bool write_heads = (out_size >= 8 * n);
    float2* out_mu = (float2*)(out + 4 * n);
    float2* out_lv = (float2*)(out + 6 * n);
    int t = blockIdx.x * blockDim.x + tid;
    int stride = gridDim.x * blockDim.x;
    for (int i = t; i < n; i += stride) {
        float4 a = g_enc_acc[i];
        float inv = 1.0f / fmaxf(g_deg[i], 1.0f);
        float mu0 = a.x * inv + sc[0];
        float mu1 = a.y * inv + sc[1];
        float lv0 = a.z * inv + sc[2];
        float lv1 = a.w * inv + sc[3];
        float2 ep = eps[i];
        float z0 = mu0 + ep.x * expf(0.5f * lv0);
        float z1 = mu1 + ep.y * expf(0.5f * lv1);
        if (write_heads) {
            out_mu[i] = make_float2(mu0, mu1);
            out_lv[i] = make_float2(lv0, lv1);
        }
        float4 ra[8], rb[8];
        float* pa = (float*)ra;
        float* pb = (float*)rb;
#pragma unroll
        for (int k = 0; k < 32; k++) {
            const float* w = sw + k * 4;
            float b = w[2] * z0 + w[3] * z1;
            float aa = sb[k] + w[0] * z0 + w[1] * z1 - b;
            pa[k] = aa;
            pb[k] = b;
        }
#pragma unroll
        for (int q8 = 0; q8 < 8; q8++) {
            g_da[i * 8 + q8] = ra[q8];
            g_db[i * 8 + q8] = rb[q8];
        }
    }
}

// ---------------- finalize decoder output ----------------
__global__ void k_fin2(const float* __restrict__ b3, float4* __restrict__ out, int n) {
    int t = blockIdx.x * blockDim.x + threadIdx.x;
    int stride = gridDim.x * blockDim.x;
    float c0 = b3[0], c1 = b3[1], c2 = b3[2], c3 = b3[3];
    for (int i = t; i < n; i += stride) {
        float4 a = g_dec_acc[i];
        float d = g_deg[i];
        float4 o;
        if (d > 0.5f) {
            float inv = 1.0f / d;
            o = make_float4(a.x * inv + c0, a.y * inv + c1, a.z * inv + c2, a.w * inv + c3);
        } else {
            o = make_float4(0.f, 0.f, 0.f, 0.f);
        }
        out[i] = o;
    }
}

// ---------------- launch ----------------
extern "C" void kernel_launch(void* const* d_in, const int* in_sizes, int n_in,
                              void* d_out, int out_size) {
    const float* x     = (const float*)d_in[0];
    const float* eps   = (const float*)d_in[1];
    const float* gamma = (const float*)d_in[2];
    const float* beta  = (const float*)d_in[3];
    const float* ew1   = (const float*)d_in[4];
    const float* eb1   = (const float*)d_in[5];
    const float* ew2   = (const float*)d_in[6];
    const float* eb2   = (const float*)d_in[7];
    const float* muw   = (const float*)d_in[8];
    const float* mub   = (const float*)d_in[9];
    const float* vw    = (const float*)d_in[10];
    const float* vb    = (const float*)d_in[11];
    const float* dw1   = (const float*)d_in[12];
    const float* db1   = (const float*)d_in[13];
    const float* dw2   = (const float*)d_in[14];
    const float* db2   = (const float*)d_in[15];
    const float* dw3   = (const float*)d_in[16];
    const float* db3   = (const float*)d_in[17];
    const int*   ei    = (const int*)d_in[18];   // int32

    int n = in_sizes[0] / 4;
    int E = in_sizes[18] / 2;
    float* out = (float*)d_out;

    k_zero<<<256, 256>>>(n);
    k_bn_reduce<<<160, 256>>>((const float4*)x, n);
    k_prep_enc<<<256, 256>>>((const float4*)x, ew1, eb1, gamma, beta, n);

    int eblocks = 1184;   // grid-stride over 12500 tiles of 256 edges
    k_edge<0><<<eblocks, 128>>>(ei, E, n, ew2, eb2, muw, vw);
    k_fin1<<<256, 256>>>((const float2*)eps, mub, vb, dw1, db1, out, n, out_size);
    k_edge<1><<<eblocks, 128>>>(ei, E, n, dw2, db2, dw3, dw3 + 64);
    k_fin2<<<128, 256>>>(db3, (float4*)out, n);
}

// round 15
// speedup vs baseline: 2.1833x; 1.1255x over previous
#include <cuda_runtime.h>
#include <cstdint>

#define MAXN 100000
typedef unsigned long long ull;

// ---------------- device scratch (static: no allocations allowed) ----------------
__device__ float  g_bn[8];              // sum[4], sumsq[4]
__device__ float  g_deg[MAXN];
__device__ float4 g_enc_acc[MAXN];      // {mu0,mu1,lv0,lv1} sums
__device__ float4 g_dec_acc[MAXN];      // {o0..o3} sums
__device__ float4 g_ea[MAXN * 8];       // A@xn + b1  (N x 32)
__device__ float4 g_eb[MAXN * 8];       // B@xn       (N x 32)
__device__ float4 g_da[MAXN * 8];       // decoder A@z + b1
__device__ float4 g_db[MAXN * 8];       // decoder B@z

__device__ __forceinline__ void red_add_v4(float* p, float a, float b, float c, float d) {
    asm volatile("red.global.add.v4.f32 [%0], {%1,%2,%3,%4};"
                 :: "l"(p), "f"(a), "f"(b), "f"(c), "f"(d) : "memory");
}
__device__ __forceinline__ void red_add_f32(float* p, float a) {
    asm volatile("red.global.add.f32 [%0], %1;" :: "l"(p), "f"(a) : "memory");
}
__device__ __forceinline__ ull pack2(float lo, float hi) {
    ull d;
    asm("mov.b64 %0, {%1, %2};" : "=l"(d) : "f"(lo), "f"(hi));
    return d;
}
__device__ __forceinline__ void unpack2(ull v, float& lo, float& hi) {
    asm("mov.b64 {%0, %1}, %2;" : "=f"(lo), "=f"(hi) : "l"(v));
}
// pack two f32 to f16x2: hi -> high half, lo -> low half
__device__ __forceinline__ uint32_t cvt_h2(float hi, float lo) {
    uint32_t r;
    asm("cvt.rn.f16x2.f32 %0, %1, %2;" : "=r"(r) : "f"(hi), "f"(lo));
    return r;
}
__device__ __forceinline__ uint32_t smem_u32(const void* p) {
    uint32_t a;
    asm("{ .reg .u64 t; cvta.to.shared.u64 t, %1; cvt.u32.u64 %0, t; }" : "=r"(a) : "l"(p));
    return a;
}
__device__ __forceinline__ void ldsm_x4(uint32_t& r0, uint32_t& r1, uint32_t& r2, uint32_t& r3,
                                        uint32_t addr) {
    asm volatile("ldmatrix.sync.aligned.m8n8.x4.shared.b16 {%0,%1,%2,%3}, [%4];"
                 : "=r"(r0), "=r"(r1), "=r"(r2), "=r"(r3) : "r"(addr));
}

// ---------------- zero accumulators ----------------
__global__ void k_zero(int n) {
    int t = blockIdx.x * blockDim.x + threadIdx.x;
    int stride = gridDim.x * blockDim.x;
    float4 z = make_float4(0.f, 0.f, 0.f, 0.f);
    for (int i = t; i < n; i += stride) {
        g_enc_acc[i] = z;
        g_dec_acc[i] = z;
        g_deg[i] = 0.f;
    }
    if (t < 8) g_bn[t] = 0.f;
}

// ---------------- batchnorm statistics ----------------
__global__ void k_bn_reduce(const float4* __restrict__ x, int n) {
    int t = blockIdx.x * blockDim.x + threadIdx.x;
    int stride = gridDim.x * blockDim.x;
    float s[4] = {0.f, 0.f, 0.f, 0.f};
    float q[4] = {0.f, 0.f, 0.f, 0.f};
    for (int i = t; i < n; i += stride) {
        float4 v = x[i];
        s[0] += v.x; q[0] += v.x * v.x;
        s[1] += v.y; q[1] += v.y * v.y;
        s[2] += v.z; q[2] += v.z * v.z;
        s[3] += v.w; q[3] += v.w * v.w;
    }
#pragma unroll
    for (int o = 16; o > 0; o >>= 1) {
#pragma unroll
        for (int c = 0; c < 4; c++) {
            s[c] += __shfl_down_sync(0xffffffffu, s[c], o);
            q[c] += __shfl_down_sync(0xffffffffu, q[c], o);
        }
    }
    if ((threadIdx.x & 31) == 0) {
#pragma unroll
        for (int c = 0; c < 4; c++) {
            atomicAdd(&g_bn[c], s[c]);
            atomicAdd(&g_bn[4 + c], q[c]);
        }
    }
}

// ---------------- encoder node precompute: BN + linearized layer 1 ----------------
__global__ void k_prep_enc(const float4* __restrict__ x,
                           const float* __restrict__ w1, const float* __restrict__ b1,
                           const float* __restrict__ gamma, const float* __restrict__ beta,
                           int n) {
    __shared__ float sw[256];   // enc_w1 (32 x 8) row-major
    __shared__ float sb1[32];
    __shared__ float sm[4], ss[4], sbt[4];
    int tid = threadIdx.x;
    if (tid < 256) sw[tid] = w1[tid];
    if (tid < 32)  sb1[tid] = b1[tid];
    if (tid < 4) {
        float m = g_bn[tid] / (float)n;
        float var = g_bn[4 + tid] / (float)n - m * m;
        sm[tid]  = m;
        ss[tid]  = rsqrtf(var + 1e-5f) * gamma[tid];
        sbt[tid] = beta[tid];
    }
    __syncthreads();
    int t = blockIdx.x * blockDim.x + tid;
    int stride = gridDim.x * blockDim.x;
    for (int i = t; i < n; i += stride) {
        float4 xv = x[i];
        float x0 = (xv.x - sm[0]) * ss[0] + sbt[0];
        float x1 = (xv.y - sm[1]) * ss[1] + sbt[1];
        float x2 = (xv.z - sm[2]) * ss[2] + sbt[2];
        float x3 = (xv.w - sm[3]) * ss[3] + sbt[3];
        float4 ra[8], rb[8];
        float* pa = (float*)ra;
        float* pb = (float*)rb;
#pragma unroll
        for (int k = 0; k < 32; k++) {
            const float* w = sw + k * 8;
            float b = w[4] * x0 + w[5] * x1 + w[6] * x2 + w[7] * x3;
            float a = sb1[k] + w[0] * x0 + w[1] * x1 + w[2] * x2 + w[3] * x3 - b;
            pa[k] = a;
            pb[k] = b;
        }
#pragma unroll
        for (int q8 = 0; q8 < 8; q8++) {
            g_ea[i * 8 + q8] = ra[q8];
            g_eb[i * 8 + q8] = rb[q8];
        }
    }
}

// ---------------- per-edge kernel: full-line fp16 gather -> ldmatrix f16 MMA -> chained f16 MMA -> RED ----
// Warp-tile = 64 edges. A = fp16 u rows [64x32] in warp-private smem, row stride 80B.
// Gather: 8 lanes per row, one float4 each -> every LDG.128 covers 4 COMPLETE 128B
// lines (1 wavefront per node row, the L1 floor). Store u chunk via STS.64.
// GEMM1: m16n8k16 f16 (A via ldmatrix.x4 — conflict-free at stride 20 words).
// GEMM2 (projection): relu(C1) in-lane cvt to f16 A-frags, P[32x8] persistent B-frags.
// Outputs in lanes tg=0/1; one 64-bit shfl pairs them; RED v4 + deg.
#define RSH 40   // halves per stage row (80B)
template <int PHASE>
__global__ void __launch_bounds__(128, 4)
k_edge(const int* __restrict__ ei, int E, int n,
       const float* __restrict__ w2, const float* __restrict__ b2,
       const float* __restrict__ pA, const float* __restrict__ pB) {
    __shared__ __align__(16) uint16_t su[4 * 64 * RSH];   // 20.5KB
    __shared__ float s_b2[32];
    int tid = threadIdx.x;
    int warp = tid >> 5, lane = tid & 31;
    int g = lane >> 2, tg = lane & 3;

    if (tid < 32) s_b2[tid] = b2[tid];

    // GEMM1 persistent B fragments (f16): bf0/bf1[nt][ks], n = 8nt+g, k = ks*16 + ...
    uint32_t bf0[4][2], bf1[4][2];
#pragma unroll
    for (int nt = 0; nt < 4; nt++)
#pragma unroll
        for (int ks = 0; ks < 2; ks++) {
            const float* wr = w2 + (8 * nt + g) * 32 + 16 * ks;
            bf0[nt][ks] = cvt_h2(wr[2 * tg + 1], wr[2 * tg]);
            bf1[nt][ks] = cvt_h2(wr[2 * tg + 9], wr[2 * tg + 8]);
        }

    // GEMM2 persistent B fragments: P[k][n], n = g (cols 0-3 real, 4-7 zero)
    auto Pv = [&](int k) -> float {
        return (g == 0) ? pA[k] : (g == 1) ? pA[32 + k]
             : (g == 2) ? pB[k] : (g == 3) ? pB[32 + k] : 0.f;
    };
    uint32_t pb0[2], pb1[2];
#pragma unroll
    for (int m = 0; m < 2; m++) {
        int k0 = 16 * m + 2 * tg;
        pb0[m] = cvt_h2(Pv(k0 + 1), Pv(k0));
        pb1[m] = cvt_h2(Pv(k0 + 9), Pv(k0 + 8));
    }
    __syncthreads();

    const float4* fa = (PHASE == 0) ? g_ea : g_da;
    const float4* fb = (PHASE == 0) ? g_eb : g_db;
    float* acc = (PHASE == 0) ? (float*)g_enc_acc : (float*)g_dec_acc;

    uint16_t* stage = su + warp * 64 * RSH;
    uint32_t stage_s = smem_u32(stage);
    int c8 = lane & 7, rsub = lane >> 3;   // gather: 8 lanes per row (full line), 4 rows per pass
    // ldmatrix lane address: matrix = lane>>3 (0..3), row-in-8 = lane&7
    int lm_mat = lane >> 3, lm_r8 = lane & 7;
    uint32_t lm_base = stage_s + (uint32_t)((lm_mat & 1) * 8 + lm_r8) * (RSH * 2)
                     + (uint32_t)(lm_mat >> 1) * 16;
    int ntiles = (E + 255) >> 8;   // 256 edges per block-tile (64 per warp)

    for (int t = blockIdx.x; t < ntiles; t += gridDim.x) {
        int base = (t << 8) + (warp << 6);
        int eA = base + lane;
        int eB = base + 32 + lane;
        bool okA = (eA < E), okB = (eB < E);
        int eAc = okA ? eA : (E - 1);
        int eBc = okB ? eB : (E - 1);
        unsigned jA = (unsigned)ei[eAc];
        unsigned iA = (unsigned)ei[E + eAc];
        unsigned jB = (unsigned)ei[eBc];
        unsigned iB = (unsigned)ei[E + eBc];
        okA = okA && (jA < (unsigned)n) && (iA < (unsigned)n);
        okB = okB && (jB < (unsigned)n) && (iB < (unsigned)n);
        unsigned jsA = okA ? jA : 0u, isA = okA ? iA : 0u;
        unsigned jsB = okB ? jB : 0u, isB = okB ? iB : 0u;
        unsigned okiA = okA ? 1u : 0u, okiB = okB ? 1u : 0u;

        __syncwarp();   // stage is warp-private; prior iter reads done
#pragma unroll
        for (int h = 0; h < 2; h++) {
#pragma unroll
            for (int p = 0; p < 8; p++) {
                int er = p * 4 + rsub;   // 4 rows per pass
                unsigned nd = __shfl_sync(0xffffffffu, h ? isB : isA, er);
                unsigned ns = __shfl_sync(0xffffffffu, h ? jsB : jsA, er);
                float4 a = fa[nd * 8 + c8];
                float4 b = fb[ns * 8 + c8];
                uint2 w;
                w.x = cvt_h2(fmaxf(a.y + b.y, 0.f), fmaxf(a.x + b.x, 0.f));
                w.y = cvt_h2(fmaxf(a.w + b.w, 0.f), fmaxf(a.z + b.z, 0.f));
                *(uint2*)(stage + (h * 32 + er) * RSH + c8 * 4) = w;
            }
        }
        __syncwarp();

#pragma unroll
        for (int mt = 0; mt < 4; mt++) {
            // ---- GEMM1: v = W2 @ u + b2 (bias-seeded), A via ldmatrix ----
            float c[4][4];
#pragma unroll
            for (int nt = 0; nt < 4; nt++) {
                float bb0 = s_b2[8 * nt + 2 * tg];
                float bb1 = s_b2[8 * nt + 2 * tg + 1];
                c[nt][0] = bb0; c[nt][1] = bb1;
                c[nt][2] = bb0; c[nt][3] = bb1;
            }
            uint32_t lm_addr = lm_base + (uint32_t)(mt * 16) * (RSH * 2);
#pragma unroll
            for (int ks = 0; ks < 2; ks++) {
                uint32_t a0, a1, a2, a3;
                ldsm_x4(a0, a1, a2, a3, lm_addr + ks * 32);
#pragma unroll
                for (int nt = 0; nt < 4; nt++) {
                    asm volatile(
                        "mma.sync.aligned.m16n8k16.row.col.f32.f16.f16.f32 "
                        "{%0,%1,%2,%3}, {%4,%5,%6,%7}, {%8,%9}, {%0,%1,%2,%3};"
                        : "+f"(c[nt][0]), "+f"(c[nt][1]), "+f"(c[nt][2]), "+f"(c[nt][3])
                        : "r"(a0), "r"(a1), "r"(a2), "r"(a3),
                          "r"(bf0[nt][ks]), "r"(bf1[nt][ks]));
                }
            }

            // ---- GEMM2: p = relu(v) @ P  (chained fp16, in-lane A-frags) ----
            float d[4] = {0.f, 0.f, 0.f, 0.f};
#pragma unroll
            for (int m = 0; m < 2; m++) {
                int n0 = 2 * m, n1 = 2 * m + 1;
                uint32_t a0 = cvt_h2(fmaxf(c[n0][1], 0.f), fmaxf(c[n0][0], 0.f));
                uint32_t a1 = cvt_h2(fmaxf(c[n0][3], 0.f), fmaxf(c[n0][2], 0.f));
                uint32_t a2 = cvt_h2(fmaxf(c[n1][1], 0.f), fmaxf(c[n1][0], 0.f));
                uint32_t a3 = cvt_h2(fmaxf(c[n1][3], 0.f), fmaxf(c[n1][2], 0.f));
                asm volatile(
                    "mma.sync.aligned.m16n8k16.row.col.f32.f16.f16.f32 "
                    "{%0,%1,%2,%3}, {%4,%5,%6,%7}, {%8,%9}, {%0,%1,%2,%3};"
                    : "+f"(d[0]), "+f"(d[1]), "+f"(d[2]), "+f"(d[3])
                    : "r"(a0), "r"(a1), "r"(a2), "r"(a3),
                      "r"(pb0[m]), "r"(pb1[m]));
            }

            // ---- epilogue: D rows g (d0,d1), g+8 (d2,d3); tg0 = mu01, tg1 = lv01 ----
            ull pk0 = pack2(d[0], d[1]);
            ull pk1 = pack2(d[2], d[3]);
            ull o0 = __shfl_xor_sync(0xffffffffu, pk0, 1);
            ull o1 = __shfl_xor_sync(0xffffffffu, pk1, 1);

            unsigned isH  = (mt < 2) ? isA : isB;
            unsigned okiH = (mt < 2) ? okiA : okiB;
            int rh = (mt & 1) * 16 + g;
            unsigned iR0  = __shfl_sync(0xffffffffu, isH,  rh);
            unsigned okR0 = __shfl_sync(0xffffffffu, okiH, rh);
            unsigned iR1  = __shfl_sync(0xffffffffu, isH,  rh + 8);
            unsigned okR1 = __shfl_sync(0xffffffffu, okiH, rh + 8);
            if (tg == 0) {
                float m0, m1, l0, l1;
                if (okR0) {
                    unpack2(pk0, m0, m1);
                    unpack2(o0, l0, l1);
                    red_add_v4(acc + 4 * iR0, m0, m1, l0, l1);
                }
                if (okR1) {
                    unpack2(pk1, m0, m1);
                    unpack2(o1, l0, l1);
                    red_add_v4(acc + 4 * iR1, m0, m1, l0, l1);
                }
            } else if (PHASE == 0 && tg == 1) {
                if (okR0) red_add_f32(&g_deg[iR0], 1.0f);
                if (okR1) red_add_f32(&g_deg[iR1], 1.0f);
            }
        }
    }
}

// ---------------- finalize encoder: mu/logvar, reparam z, decoder layer-1 precompute ----------------
__global__ void k_fin1(const float2* __restrict__ eps,
                       const float* __restrict__ mu_b, const float* __restrict__ var_b,
                       const float* __restrict__ dw1, const float* __restrict__ db1,
                       float* __restrict__ out, int n, int out_size) {
    __shared__ float sw[128];   // dec_w1 (32 x 4)
    __shared__ float sb[32];
    __shared__ float sc[4];
    int tid = threadIdx.x;
    if (tid < 128) sw[tid] = dw1[tid];
    if (tid < 32)  sb[tid] = db1[tid];
    if (tid < 2) { sc[tid] = mu_b[tid]; sc[2 + tid] = var_b[tid]; }
    __syncthreads();
    bool write_heads = (out_size >= 8 * n);
    float2* out_mu = (float2*)(out + 4 * n);
    float2* out_lv = (float2*)(out + 6 * n);
    int t = blockIdx.x * blockDim.x + tid;
    int stride = gridDim.x * blockDim.x;
    for (int i = t; i < n; i += stride) {
        float4 a = g_enc_acc[i];
        float inv = 1.0f / fmaxf(g_deg[i], 1.0f);
        float mu0 = a.x * inv + sc[0];
        float mu1 = a.y * inv + sc[1];
        float lv0 = a.z * inv + sc[2];
        float lv1 = a.w * inv + sc[3];
        float2 ep = eps[i];
        float z0 = mu0 + ep.x * expf(0.5f * lv0);
        float z1 = mu1 + ep.y * expf(0.5f * lv1);
        if (write_heads) {
            out_mu[i] = make_float2(mu0, mu1);
            out_lv[i] = make_float2(lv0, lv1);
        }
        float4 ra[8], rb[8];
        float* pa = (float*)ra;
        float* pb = (float*)rb;
#pragma unroll
        for (int k = 0; k < 32; k++) {
            const float* w = sw + k * 4;
            float b = w[2] * z0 + w[3] * z1;
            float aa = sb[k] + w[0] * z0 + w[1] * z1 - b;
            pa[k] = aa;
            pb[k] = b;
        }
#pragma unroll
        for (int q8 = 0; q8 < 8; q8++) {
            g_da[i * 8 + q8] = ra[q8];
            g_db[i * 8 + q8] = rb[q8];
        }
    }
}

// ---------------- finalize decoder output ----------------
__global__ void k_fin2(const float* __restrict__ b3, float4* __restrict__ out, int n) {
    int t = blockIdx.x * blockDim.x + threadIdx.x;
    int stride = gridDim.x * blockDim.x;
    float c0 = b3[0], c1 = b3[1], c2 = b3[2], c3 = b3[3];
    for (int i = t; i < n; i += stride) {
        float4 a = g_dec_acc[i];
        float d = g_deg[i];
        float4 o;
        if (d > 0.5f) {
            float inv = 1.0f / d;
            o = make_float4(a.x * inv + c0, a.y * inv + c1, a.z * inv + c2, a.w * inv + c3);
        } else {
            o = make_float4(0.f, 0.f, 0.f, 0.f);
        }
        out[i] = o;
    }
}

// ---------------- launch ----------------
extern "C" void kernel_launch(void* const* d_in, const int* in_sizes, int n_in,
                              void* d_out, int out_size) {
    const float* x     = (const float*)d_in[0];
    const float* eps   = (const float*)d_in[1];
    const float* gamma = (const float*)d_in[2];
    const float* beta  = (const float*)d_in[3];
    const float* ew1   = (const float*)d_in[4];
    const float* eb1   = (const float*)d_in[5];
    const float* ew2   = (const float*)d_in[6];
    const float* eb2   = (const float*)d_in[7];
    const float* muw   = (const float*)d_in[8];
    const float* mub   = (const float*)d_in[9];
    const float* vw    = (const float*)d_in[10];
    const float* vb    = (const float*)d_in[11];
    const float* dw1   = (const float*)d_in[12];
    const float* db1   = (const float*)d_in[13];
    const float* dw2   = (const float*)d_in[14];
    const float* db2   = (const float*)d_in[15];
    const float* dw3   = (const float*)d_in[16];
    const float* db3   = (const float*)d_in[17];
    const int*   ei    = (const int*)d_in[18];   // int32

    int n = in_sizes[0] / 4;
    int E = in_sizes[18] / 2;
    float* out = (float*)d_out;

    k_zero<<<256, 256>>>(n);
    k_bn_reduce<<<160, 256>>>((const float4*)x, n);
    k_prep_enc<<<256, 256>>>((const float4*)x, ew1, eb1, gamma, beta, n);

    int eblocks = 1184;   // grid-stride over 12500 tiles of 256 edges
    k_edge<0><<<eblocks, 128>>>(ei, E, n, ew2, eb2, muw, vw);
    k_fin1<<<256, 256>>>((const float2*)eps, mub, vb, dw1, db1, out, n, out_size);
    k_edge<1><<<eblocks, 128>>>(ei, E, n, dw2, db2, dw3, dw3 + 64);
    k_fin2<<<128, 256>>>(db3, (float4*)out, n);
}